// round 9
// baseline (speedup 1.0000x reference)
#include <cuda_runtime.h>
#include <cuda_fp16.h>
#include <cstdint>

#define BATCH 256
#define SEQ   197
#define SN    196
#define DIM   768
#define GRID  14
#define MQK   (BATCH*SEQ)
#define MH    (BATCH*SN)
#define MV    (BATCH*64)
#define H60   60
#define K2    1536

__device__ float g_q [(size_t)MQK * DIM];
__device__ float g_k [(size_t)MQK * DIM];
__device__ float g_vs[(size_t)MV  * DIM];
__device__ float g_h1[(size_t)MH  * H60];
__device__ float g_sample[(size_t)MH * 2];
__device__ float g_coords[(size_t)MH * 2];

// pack (x, y) -> half2 {lo=x, hi=y}, round-to-nearest
__device__ __forceinline__ uint32_t h2pack(float x, float y) {
    uint32_t r;
    asm("cvt.rn.f16x2.f32 %0, %1, %2;" : "=r"(r) : "f"(y), "f"(x));
    return r;
}

// fp16 mma m16n8k16, f32 accumulate
__device__ __forceinline__ void mma_f16(float (&d)[4], const uint32_t (&a)[4], const uint32_t (&b)[2]) {
    asm volatile(
        "mma.sync.aligned.m16n8k16.row.col.f32.f16.f16.f32 "
        "{%0,%1,%2,%3}, {%4,%5,%6,%7}, {%8,%9}, {%0,%1,%2,%3};\n"
        : "+f"(d[0]), "+f"(d[1]), "+f"(d[2]), "+f"(d[3])
        : "r"(a[0]), "r"(a[1]), "r"(a[2]), "r"(a[3]), "r"(b[0]), "r"(b[1]));
}

__device__ __forceinline__ void ldsm_x4(uint32_t& r0, uint32_t& r1, uint32_t& r2, uint32_t& r3, uint32_t addr) {
    asm volatile("ldmatrix.sync.aligned.m8n8.x4.shared.b16 {%0,%1,%2,%3}, [%4];"
                 : "=r"(r0), "=r"(r1), "=r"(r2), "=r"(r3) : "r"(addr));
}

// load 32 floats -> 16 packed h2 regs
__device__ __forceinline__ void ld_pack32(uint32_t (&u)[16], const float* p) {
    #pragma unroll
    for (int i = 0; i < 4; i++) {
        float4 a = *reinterpret_cast<const float4*>(p + i*8);
        float4 b = *reinterpret_cast<const float4*>(p + i*8 + 4);
        u[i*4+0] = h2pack(a.x, a.y); u[i*4+1] = h2pack(a.z, a.w);
        u[i*4+2] = h2pack(b.x, b.y); u[i*4+3] = h2pack(b.z, b.w);
    }
}

// ============================================================
// FP16 tensor GEMM: Y[r,e] = sum_d A[r,d]*W[e,d] + bias[e]
// Block 128x128, K-chunk 64 halves (32 uint32/row). 8 warps 2Mx4N.
// grid: rowTile*12 + (z*6 + colTile), col/z fastest (L2 reuse of X).
// ============================================================
__global__ __launch_bounds__(256) void k_gemm_qk_t(
    const float* __restrict__ X,
    const float* __restrict__ Wq, const float* __restrict__ bq,
    const float* __restrict__ Wk, const float* __restrict__ bk)
{
    const int bx  = blockIdx.x;
    const int rt  = bx / 12;
    const int rem = bx - rt * 12;
    const int ct  = rem % 6;
    const int zz  = rem / 6;

    const float* W    = zz ? Wk : Wq;
    const float* bias = zz ? bk : bq;
    float*       Y    = zz ? g_k : g_q;

    __shared__ __align__(16) uint32_t As[128][36];
    __shared__ __align__(16) uint32_t Bs[128][36];

    const int tid  = threadIdx.x;
    const int lane = tid & 31;
    const int wid  = tid >> 5;
    const int warpM = wid & 1;
    const int warpN = wid >> 1;

    const int row0 = rt * 128;
    const int col0 = ct * 128;

    const int ldr = tid >> 1;
    const int ldc = (tid & 1) * 16;        // uint32 col base
    const int ec  = (tid & 1) * 32;        // element col base

    const float* Ap = X + (size_t)(row0 + ldr) * DIM + ec;
    const float* Bp = W + (size_t)(col0 + ldr) * DIM + ec;

    const uint32_t As_addr = (uint32_t)__cvta_generic_to_shared(&As[0][0]);
    const uint32_t Bs_addr = (uint32_t)__cvta_generic_to_shared(&Bs[0][0]);
    const uint32_t a_base = As_addr + (((warpM*64 + (lane & 15)) * 36 + ((lane >> 4) << 2)) << 2);
    const uint32_t b_base = Bs_addr + (((warpN*32 + (lane & 15)) * 36 + ((lane >> 4) << 2)) << 2);

    float acc[4][4][4];
    #pragma unroll
    for (int mt = 0; mt < 4; mt++)
        #pragma unroll
        for (int nt = 0; nt < 4; nt++)
            #pragma unroll
            for (int i = 0; i < 4; i++) acc[mt][nt][i] = 0.f;

    uint32_t ua[16], ub[16];
    ld_pack32(ua, Ap);
    ld_pack32(ub, Bp);

    for (int k0 = 0; k0 < DIM; k0 += 64) {
        #pragma unroll
        for (int i = 0; i < 4; i++) {
            *reinterpret_cast<uint4*>(&As[ldr][ldc + i*4]) = *reinterpret_cast<uint4*>(&ua[i*4]);
            *reinterpret_cast<uint4*>(&Bs[ldr][ldc + i*4]) = *reinterpret_cast<uint4*>(&ub[i*4]);
        }
        __syncthreads();
        if (k0 + 64 < DIM) {
            ld_pack32(ua, Ap + k0 + 64);
            ld_pack32(ub, Bp + k0 + 64);
        }
        #pragma unroll
        for (int ks = 0; ks < 4; ks++) {
            uint32_t af[4][4], bf[4][2];
            #pragma unroll
            for (int mt = 0; mt < 4; mt++)
                ldsm_x4(af[mt][0], af[mt][1], af[mt][2], af[mt][3],
                        a_base + ((mt*16*36 + ks*8) << 2));
            #pragma unroll
            for (int nt2 = 0; nt2 < 2; nt2++) {
                uint32_t r0, r1, r2, r3;
                ldsm_x4(r0, r1, r2, r3, b_base + ((nt2*16*36 + ks*8) << 2));
                bf[2*nt2  ][0] = r0; bf[2*nt2+1][0] = r1;
                bf[2*nt2  ][1] = r2; bf[2*nt2+1][1] = r3;
            }
            #pragma unroll
            for (int mt = 0; mt < 4; mt++)
                #pragma unroll
                for (int nt = 0; nt < 4; nt++)
                    mma_f16(acc[mt][nt], af[mt], bf[nt]);
        }
        __syncthreads();
    }

    #pragma unroll
    for (int nt = 0; nt < 4; nt++) {
        const int c = col0 + warpN*32 + nt*8 + 2*(lane & 3);
        const float b0v = bias[c];
        const float b1v = bias[c + 1];
        #pragma unroll
        for (int mt = 0; mt < 4; mt++) {
            const int r = row0 + warpM*64 + mt*16 + (lane >> 2);
            float2 o0 = make_float2(acc[mt][nt][0] + b0v, acc[mt][nt][1] + b1v);
            float2 o1 = make_float2(acc[mt][nt][2] + b0v, acc[mt][nt][3] + b1v);
            *reinterpret_cast<float2*>(Y + (size_t)r * DIM + c)       = o0;
            *reinterpret_cast<float2*>(Y + (size_t)(r + 8) * DIM + c) = o1;
        }
    }
}

// ============================================================
// FP16 V projection on the 64 reachable tokens per batch.
// ============================================================
__global__ __launch_bounds__(256) void k_gemm_v_t(
    const float* __restrict__ X,
    const float* __restrict__ Wv, const float* __restrict__ bv)
{
    __shared__ __align__(16) uint32_t As[128][36];
    __shared__ __align__(16) uint32_t Bs[128][36];

    const int bx = blockIdx.x;
    const int rt = bx / 6;
    const int ct = bx - rt * 6;

    const int tid  = threadIdx.x;
    const int lane = tid & 31;
    const int wid  = tid >> 5;
    const int warpM = wid & 1;
    const int warpN = wid >> 1;

    const int row0 = rt * 128;
    const int col0 = ct * 128;

    const int ldr = tid >> 1;
    const int ldc = (tid & 1) * 16;
    const int ec  = (tid & 1) * 32;

    const int r_g = row0 + ldr;
    const int bb  = r_g >> 6;
    const int jj  = r_g & 63;
    const int token = 1 + (6 + (jj >> 3)) * GRID + (6 + (jj & 7));
    const float* Ap = X + (size_t)(bb * SEQ + token) * DIM + ec;
    const float* Bp = Wv + (size_t)(col0 + ldr) * DIM + ec;

    const uint32_t As_addr = (uint32_t)__cvta_generic_to_shared(&As[0][0]);
    const uint32_t Bs_addr = (uint32_t)__cvta_generic_to_shared(&Bs[0][0]);
    const uint32_t a_base = As_addr + (((warpM*64 + (lane & 15)) * 36 + ((lane >> 4) << 2)) << 2);
    const uint32_t b_base = Bs_addr + (((warpN*32 + (lane & 15)) * 36 + ((lane >> 4) << 2)) << 2);

    float acc[4][4][4];
    #pragma unroll
    for (int mt = 0; mt < 4; mt++)
        #pragma unroll
        for (int nt = 0; nt < 4; nt++)
            #pragma unroll
            for (int i = 0; i < 4; i++) acc[mt][nt][i] = 0.f;

    uint32_t ua[16], ub[16];
    ld_pack32(ua, Ap);
    ld_pack32(ub, Bp);

    for (int k0 = 0; k0 < DIM; k0 += 64) {
        #pragma unroll
        for (int i = 0; i < 4; i++) {
            *reinterpret_cast<uint4*>(&As[ldr][ldc + i*4]) = *reinterpret_cast<uint4*>(&ua[i*4]);
            *reinterpret_cast<uint4*>(&Bs[ldr][ldc + i*4]) = *reinterpret_cast<uint4*>(&ub[i*4]);
        }
        __syncthreads();
        if (k0 + 64 < DIM) {
            ld_pack32(ua, Ap + k0 + 64);
            ld_pack32(ub, Bp + k0 + 64);
        }
        #pragma unroll
        for (int ks = 0; ks < 4; ks++) {
            uint32_t af[4][4], bf[4][2];
            #pragma unroll
            for (int mt = 0; mt < 4; mt++)
                ldsm_x4(af[mt][0], af[mt][1], af[mt][2], af[mt][3],
                        a_base + ((mt*16*36 + ks*8) << 2));
            #pragma unroll
            for (int nt2 = 0; nt2 < 2; nt2++) {
                uint32_t r0, r1, r2, r3;
                ldsm_x4(r0, r1, r2, r3, b_base + ((nt2*16*36 + ks*8) << 2));
                bf[2*nt2  ][0] = r0; bf[2*nt2+1][0] = r1;
                bf[2*nt2  ][1] = r2; bf[2*nt2+1][1] = r3;
            }
            #pragma unroll
            for (int mt = 0; mt < 4; mt++)
                #pragma unroll
                for (int nt = 0; nt < 4; nt++)
                    mma_f16(acc[mt][nt], af[mt], bf[nt]);
        }
        __syncthreads();
    }

    #pragma unroll
    for (int nt = 0; nt < 4; nt++) {
        const int c = col0 + warpN*32 + nt*8 + 2*(lane & 3);
        const float b0v = bv[c];
        const float b1v = bv[c + 1];
        #pragma unroll
        for (int mt = 0; mt < 4; mt++) {
            const int r = row0 + warpM*64 + mt*16 + (lane >> 2);
            float2 o0 = make_float2(acc[mt][nt][0] + b0v, acc[mt][nt][1] + b1v);
            float2 o1 = make_float2(acc[mt][nt][2] + b0v, acc[mt][nt][3] + b1v);
            *reinterpret_cast<float2*>(g_vs + (size_t)r * DIM + c)       = o0;
            *reinterpret_cast<float2*>(g_vs + (size_t)(r + 8) * DIM + c) = o1;
        }
    }
}

// ============================================================
// FP16 MLP layer 1: h1 = relu(concat(q_nc,k_nc) @ W1^T + b1)
// M=50176, K=1536 (24 chunks of 64), N=60 (tile 64, guarded).
// Block 128x64; 8 warps = 4(M) x 2(N).
// ============================================================
__global__ __launch_bounds__(256) void k_gemm_h1_t(
    const float* __restrict__ W1, const float* __restrict__ b1)
{
    __shared__ __align__(16) uint32_t As[128][36];
    __shared__ __align__(16) uint32_t Bs[64][36];

    const int tid  = threadIdx.x;
    const int lane = tid & 31;
    const int wid  = tid >> 5;
    const int warpM = wid & 3;
    const int warpN = wid >> 2;

    const int row0 = blockIdx.x * 128;

    const int ldr = tid >> 1;
    const int ldc = (tid & 1) * 16;
    const int ec  = (tid & 1) * 32;

    const int r_g = row0 + ldr;
    const int bb  = r_g / SN;
    const int tt  = r_g - bb * SN;
    const size_t aoff = (size_t)(bb * SEQ + tt + 1) * DIM + ec;

    const int ldr2 = tid >> 2;             // 0..63
    const int bc   = (tid & 3) * 8;        // uint32 col base
    const int eb   = (tid & 3) * 16;       // element col base
    const bool bvalid = (ldr2 < H60);
    const float* Bp = W1 + (size_t)ldr2 * K2 + eb;

    const uint32_t As_addr = (uint32_t)__cvta_generic_to_shared(&As[0][0]);
    const uint32_t Bs_addr = (uint32_t)__cvta_generic_to_shared(&Bs[0][0]);
    const uint32_t a_base = As_addr + (((warpM*32 + (lane & 15)) * 36 + ((lane >> 4) << 2)) << 2);
    const uint32_t b_base = Bs_addr + (((warpN*32 + (lane & 15)) * 36 + ((lane >> 4) << 2)) << 2);

    float acc[2][4][4];
    #pragma unroll
    for (int mt = 0; mt < 2; mt++)
        #pragma unroll
        for (int nt = 0; nt < 4; nt++)
            #pragma unroll
            for (int i = 0; i < 4; i++) acc[mt][nt][i] = 0.f;

    uint32_t ua[16], ub[8];
    ld_pack32(ua, g_q + aoff);
    #pragma unroll
    for (int i = 0; i < 2; i++) {
        if (bvalid) {
            float4 a = *reinterpret_cast<const float4*>(Bp + i*8);
            float4 b = *reinterpret_cast<const float4*>(Bp + i*8 + 4);
            ub[i*4+0] = h2pack(a.x, a.y); ub[i*4+1] = h2pack(a.z, a.w);
            ub[i*4+2] = h2pack(b.x, b.y); ub[i*4+3] = h2pack(b.z, b.w);
        } else { ub[i*4+0]=0u; ub[i*4+1]=0u; ub[i*4+2]=0u; ub[i*4+3]=0u; }
    }

    for (int k0 = 0; k0 < K2; k0 += 64) {
        #pragma unroll
        for (int i = 0; i < 4; i++)
            *reinterpret_cast<uint4*>(&As[ldr][ldc + i*4]) = *reinterpret_cast<uint4*>(&ua[i*4]);
        #pragma unroll
        for (int i = 0; i < 2; i++)
            *reinterpret_cast<uint4*>(&Bs[ldr2][bc + i*4]) = *reinterpret_cast<uint4*>(&ub[i*4]);
        __syncthreads();
        if (k0 + 64 < K2) {
            const int kn = k0 + 64;
            const float* base = (kn < DIM) ? (g_q + aoff + kn) : (g_k + aoff + kn - DIM);
            ld_pack32(ua, base);
            #pragma unroll
            for (int i = 0; i < 2; i++) {
                if (bvalid) {
                    float4 a = *reinterpret_cast<const float4*>(Bp + kn + i*8);
                    float4 b = *reinterpret_cast<const float4*>(Bp + kn + i*8 + 4);
                    ub[i*4+0] = h2pack(a.x, a.y); ub[i*4+1] = h2pack(a.z, a.w);
                    ub[i*4+2] = h2pack(b.x, b.y); ub[i*4+3] = h2pack(b.z, b.w);
                }
            }
        }
        #pragma unroll
        for (int ks = 0; ks < 4; ks++) {
            uint32_t af[2][4], bf[4][2];
            #pragma unroll
            for (int mt = 0; mt < 2; mt++)
                ldsm_x4(af[mt][0], af[mt][1], af[mt][2], af[mt][3],
                        a_base + ((mt*16*36 + ks*8) << 2));
            #pragma unroll
            for (int nt2 = 0; nt2 < 2; nt2++) {
                uint32_t r0, r1, r2, r3;
                ldsm_x4(r0, r1, r2, r3, b_base + ((nt2*16*36 + ks*8) << 2));
                bf[2*nt2  ][0] = r0; bf[2*nt2+1][0] = r1;
                bf[2*nt2  ][1] = r2; bf[2*nt2+1][1] = r3;
            }
            #pragma unroll
            for (int mt = 0; mt < 2; mt++)
                #pragma unroll
                for (int nt = 0; nt < 4; nt++)
                    mma_f16(acc[mt][nt], af[mt], bf[nt]);
        }
        __syncthreads();
    }

    #pragma unroll
    for (int nt = 0; nt < 4; nt++) {
        const int c = warpN*32 + nt*8 + 2*(lane & 3);
        const float b0v = (c     < H60) ? b1[c]     : 0.f;
        const float b1v = (c + 1 < H60) ? b1[c + 1] : 0.f;
        #pragma unroll
        for (int mt = 0; mt < 2; mt++) {
            const int r = row0 + warpM*32 + mt*16 + (lane >> 2);
            if (c < H60) {
                g_h1[(size_t)r * H60 + c]       = fmaxf(acc[mt][nt][0] + b0v, 0.f);
                g_h1[(size_t)(r + 8) * H60 + c] = fmaxf(acc[mt][nt][2] + b0v, 0.f);
            }
            if (c + 1 < H60) {
                g_h1[(size_t)r * H60 + c + 1]       = fmaxf(acc[mt][nt][1] + b1v, 0.f);
                g_h1[(size_t)(r + 8) * H60 + c + 1] = fmaxf(acc[mt][nt][3] + b1v, 0.f);
            }
        }
    }
}

// ============================================================
// MLP layers 2+3 (unchanged)
// ============================================================
__global__ __launch_bounds__(256) void k_mlp23(
    const float* __restrict__ W2, const float* __restrict__ b2,
    const float* __restrict__ W3, const float* __restrict__ b3)
{
    __shared__ float W2s[60*61], W3s[120], b2s[60], b3s[2], h1s[16][60], h2s[16][60];
    const int tid = threadIdx.x;
    for (int i = tid; i < 3600; i += 256) { int rr = i / 60, cc = i - rr * 60; W2s[rr*61+cc] = W2[i]; }
    if (tid < 120) W3s[tid] = W3[tid];
    if (tid < 60)  b2s[tid] = b2[tid];
    if (tid < 2)   b3s[tid] = b3[tid];
    const int r0 = blockIdx.x * 16;
    for (int i = tid; i < 960; i += 256) { int t = i / 60, c = i - t * 60; h1s[t][c] = g_h1[(size_t)(r0+t)*H60 + c]; }
    __syncthreads();
    const int tg = tid >> 6, f = tid & 63;
    if (f < H60) {
        float a0 = b2s[f], a1 = a0, a2 = a0, a3 = a0;
        #pragma unroll 4
        for (int g = 0; g < H60; g++) {
            const float w = W2s[f*61 + g];
            a0 = fmaf(w, h1s[tg*4+0][g], a0); a1 = fmaf(w, h1s[tg*4+1][g], a1);
            a2 = fmaf(w, h1s[tg*4+2][g], a2); a3 = fmaf(w, h1s[tg*4+3][g], a3);
        }
        h2s[tg*4+0][f] = fmaxf(a0, 0.f); h2s[tg*4+1][f] = fmaxf(a1, 0.f);
        h2s[tg*4+2][f] = fmaxf(a2, 0.f); h2s[tg*4+3][f] = fmaxf(a3, 0.f);
    }
    __syncthreads();
    if (tid < 32) {
        int t2 = tid >> 1, c = tid & 1;
        float s = b3s[c];
        #pragma unroll 4
        for (int g = 0; g < H60; g++) s = fmaf(W3s[c*60+g], h2s[t2][g], s);
        g_sample[(size_t)(r0+t2)*2 + c] = 1.f / (1.f + expf(-s));
    }
}

__global__ void k_coords()
{
    const int id = blockIdx.x * 256 + threadIdx.x;
    const int b = id / SN, p = id - b * SN;
    const int q1 = 2 * p, q2 = 2 * p + 1;
    float gx = (q1 < SN) ? g_sample[(size_t)(b*SN+q1)*2+0] : g_sample[(size_t)(b*SN+q1-SN)*2+1];
    float gy = (q2 < SN) ? g_sample[(size_t)(b*SN+q2)*2+0] : g_sample[(size_t)(b*SN+q2-SN)*2+1];
    g_coords[(size_t)id*2+0] = ((gx + 1.f) * (float)GRID - 1.f) * 0.5f;
    g_coords[(size_t)id*2+1] = ((gy + 1.f) * (float)GRID - 1.f) * 0.5f;
}

__global__ __launch_bounds__(256) void k_epilogue(float* __restrict__ out)
{
    const int bs = blockIdx.x, b = bs / SEQ, s = bs - b * SEQ;
    const int tid = threadIdx.x, lane = tid & 31, wid = tid >> 5;
    __shared__ float red[8];
    __shared__ float sigsh;
    const size_t qbase = (size_t)bs * DIM;
    float w[4]; size_t rowk[4], rowv[4]; bool vk[4], vv[4];

    if (s > 0) {
        const int p = s - 1;
        const float ix = g_coords[(size_t)(b*SN+p)*2+0];
        const float iy = g_coords[(size_t)(b*SN+p)*2+1];
        const float ix0f = floorf(ix), iy0f = floorf(iy);
        const float wx1 = ix - ix0f, wx0 = 1.f - wx1;
        const float wy1 = iy - iy0f, wy0 = 1.f - wy1;
        const int x0 = (int)ix0f, y0 = (int)iy0f;
        const int xs[4] = {x0, x0+1, x0, x0+1};
        const int ys[4] = {y0, y0, y0+1, y0+1};
        const float ws[4] = {wy0*wx0, wy0*wx1, wy1*wx0, wy1*wx1};
        #pragma unroll
        for (int c = 0; c < 4; c++) {
            const int x = xs[c], y = ys[c];
            const bool v = (x >= 0) && (x <= GRID-1) && (y >= 0) && (y <= GRID-1);
            vk[c] = v; w[c] = ws[c];
            rowk[c] = v ? (size_t)(b * SEQ + 1 + y * GRID + x) * DIM : 0;
            const bool v2 = v && (x >= 6) && (y >= 6);
            vv[c] = v2;
            rowv[c] = v2 ? (size_t)(b * 64 + (y-6)*8 + (x-6)) * DIM : 0;
        }
    }

    float part = 0.f, svreg[3];
    #pragma unroll
    for (int it = 0; it < 3; it++) {
        const int d = tid + it * 256;
        float skd, svd;
        if (s == 0) { skd = 1.f; svd = 1.f; }
        else {
            skd = 0.f; svd = 0.f;
            #pragma unroll
            for (int c = 0; c < 4; c++) {
                if (vk[c]) skd = fmaf(w[c], g_k[rowk[c] + d], skd);
                if (vv[c]) svd = fmaf(w[c], g_vs[rowv[c] + d], svd);
            }
        }
        svreg[it] = svd;
        part = fmaf(skd, g_q[qbase + d], part);
    }
    #pragma unroll
    for (int off = 16; off > 0; off >>= 1) part += __shfl_xor_sync(0xffffffffu, part, off);
    if (lane == 0) red[wid] = part;
    __syncthreads();
    if (tid == 0) {
        float sum = 0.f;
        #pragma unroll
        for (int i = 0; i < 8; i++) sum += red[i];
        sigsh = 1.f / (1.f + expf(-0.01f * sum));
    }
    __syncthreads();
    const float sg = sigsh;
    #pragma unroll
    for (int it = 0; it < 3; it++) out[qbase + tid + it*256] = sg * svreg[it];
}

extern "C" void kernel_launch(void* const* d_in, const int* in_sizes, int n_in,
                              void* d_out, int out_size)
{
    const float* x  = (const float*)d_in[0];
    const float* Wq = (const float*)d_in[2];  const float* bq = (const float*)d_in[3];
    const float* Wk = (const float*)d_in[4];  const float* bk = (const float*)d_in[5];
    const float* Wv = (const float*)d_in[6];  const float* bv = (const float*)d_in[7];
    const float* W1 = (const float*)d_in[8];  const float* b1 = (const float*)d_in[9];
    const float* W2 = (const float*)d_in[10]; const float* b2 = (const float*)d_in[11];
    const float* W3 = (const float*)d_in[12]; const float* b3 = (const float*)d_in[13];
    float* out = (float*)d_out;

    k_gemm_qk_t<<<394 * 12, 256>>>(x, Wq, bq, Wk, bk);
    k_gemm_v_t<<<128 * 6, 256>>>(x, Wv, bv);
    k_gemm_h1_t<<<392, 256>>>(W1, b1);
    k_mlp23<<<3136, 256>>>(W2, b2, W3, b3);
    k_coords<<<196, 256>>>();
    k_epilogue<<<MQK, 256>>>(out);
}

// round 10
// speedup vs baseline: 1.1810x; 1.1810x over previous
#include <cuda_runtime.h>
#include <cstdint>

#define BATCH 256
#define SEQ   197
#define SN    196
#define DIM   768
#define GRID  14
#define MQK   (BATCH*SEQ)
#define MH    (BATCH*SN)
#define MV    (BATCH*64)
#define H60   60
#define K2    1536

__device__ float g_q [(size_t)MQK * DIM];
__device__ float g_k [(size_t)MQK * DIM];
__device__ float g_vs[(size_t)MV  * DIM];
__device__ float g_h1[(size_t)MH  * H60];
__device__ float g_sample[(size_t)MH * 2];
__device__ float g_coords[(size_t)MH * 2];
__device__ float g_x32 [(size_t)MQK * DIM];
__device__ float g_wq32[(size_t)DIM * DIM];
__device__ float g_wk32[(size_t)DIM * DIM];
__device__ float g_wv32[(size_t)DIM * DIM];
__device__ float g_w132[(size_t)H60 * K2];

__device__ __forceinline__ uint32_t f2tf32(float f) {
    uint32_t u;
    asm("cvt.rna.tf32.f32 %0, %1;" : "=r"(u) : "f"(f));
    return u;
}
__device__ __forceinline__ float tf32r(float f) { return __uint_as_float(f2tf32(f)); }

__device__ __forceinline__ void mma_tf32(float (&d)[4], const uint32_t (&a)[4], const uint32_t (&b)[2]) {
    asm volatile(
        "mma.sync.aligned.m16n8k8.row.col.f32.tf32.tf32.f32 "
        "{%0,%1,%2,%3}, {%4,%5,%6,%7}, {%8,%9}, {%0,%1,%2,%3};\n"
        : "+f"(d[0]), "+f"(d[1]), "+f"(d[2]), "+f"(d[3])
        : "r"(a[0]), "r"(a[1]), "r"(a[2]), "r"(a[3]), "r"(b[0]), "r"(b[1]));
}

__device__ __forceinline__ void ldsm_x4(uint32_t& r0, uint32_t& r1, uint32_t& r2, uint32_t& r3, uint32_t addr) {
    asm volatile("ldmatrix.sync.aligned.m8n8.x4.shared.b16 {%0,%1,%2,%3}, [%4];"
                 : "=r"(r0), "=r"(r1), "=r"(r2), "=r"(r3) : "r"(addr));
}

// ---- one-time tf32 rounding pass: X, Wq, Wk, Wv, W1 ----
__global__ __launch_bounds__(256) void k_cvt(const float4* __restrict__ x,
    const float4* __restrict__ Wq, const float4* __restrict__ Wk,
    const float4* __restrict__ Wv, const float4* __restrict__ W1)
{
    const int i = blockIdx.x * 256 + threadIdx.x;   // 39642*256 = 10,148,352 exact
    float4 v; float4* dst;
    if (i < 9682944)       { v = x[i];             dst = reinterpret_cast<float4*>(g_x32) + i; }
    else if (i < 9830400)  { v = Wq[i - 9682944];  dst = reinterpret_cast<float4*>(g_wq32) + (i - 9682944); }
    else if (i < 9977856)  { v = Wk[i - 9830400];  dst = reinterpret_cast<float4*>(g_wk32) + (i - 9830400); }
    else if (i < 10125312) { v = Wv[i - 9977856];  dst = reinterpret_cast<float4*>(g_wv32) + (i - 9977856); }
    else                   { v = W1[i - 10125312]; dst = reinterpret_cast<float4*>(g_w132) + (i - 10125312); }
    v.x = tf32r(v.x); v.y = tf32r(v.y); v.z = tf32r(v.z); v.w = tf32r(v.w);
    *dst = v;
}

// ============================================================
// TF32 GEMM (pre-rounded inputs, no in-loop cvt): Y = A@W^T + bias
// Block 128x128, K-step 32. 8 warps 2Mx4N, warp tile 64x32, ldmatrix.
// grid: rowTile*12 + (z*6 + colTile), col/z fastest (L2 reuse of X).
// Outputs tf32-rounded (consumed rounded by h1 / epilogue).
// ============================================================
__global__ __launch_bounds__(256) void k_gemm_qk_t(
    const float* __restrict__ bq, const float* __restrict__ bk)
{
    const int bx  = blockIdx.x;
    const int rt  = bx / 12;
    const int rem = bx - rt * 12;
    const int ct  = rem % 6;
    const int zz  = rem / 6;

    const float* W    = zz ? g_wk32 : g_wq32;
    const float* bias = zz ? bk : bq;
    float*       Y    = zz ? g_k : g_q;

    __shared__ __align__(16) uint32_t As[128][36];
    __shared__ __align__(16) uint32_t Bs[128][36];

    const int tid  = threadIdx.x;
    const int lane = tid & 31;
    const int wid  = tid >> 5;
    const int warpM = wid & 1;
    const int warpN = wid >> 1;

    const int row0 = rt * 128;
    const int col0 = ct * 128;

    const int ldr = tid >> 1;
    const int ldc = (tid & 1) * 16;

    const uint4* Ap = reinterpret_cast<const uint4*>(g_x32 + (size_t)(row0 + ldr) * DIM + ldc);
    const uint4* Bp = reinterpret_cast<const uint4*>(W + (size_t)(col0 + ldr) * DIM + ldc);

    const uint32_t As_addr = (uint32_t)__cvta_generic_to_shared(&As[0][0]);
    const uint32_t Bs_addr = (uint32_t)__cvta_generic_to_shared(&Bs[0][0]);
    const uint32_t a_base = As_addr + (((warpM*64 + (lane & 15)) * 36 + ((lane >> 4) << 2)) << 2);
    const uint32_t b_base = Bs_addr + (((warpN*32 + (lane & 15)) * 36 + ((lane >> 4) << 2)) << 2);

    float acc[4][4][4];
    #pragma unroll
    for (int mt = 0; mt < 4; mt++)
        #pragma unroll
        for (int nt = 0; nt < 4; nt++)
            #pragma unroll
            for (int i = 0; i < 4; i++) acc[mt][nt][i] = 0.f;

    uint4 ra[4], rb[4];
    #pragma unroll
    for (int i = 0; i < 4; i++) { ra[i] = Ap[i]; rb[i] = Bp[i]; }

    for (int k0 = 0; k0 < DIM; k0 += 32) {
        #pragma unroll
        for (int i = 0; i < 4; i++) {
            *reinterpret_cast<uint4*>(&As[ldr][ldc + i*4]) = ra[i];
            *reinterpret_cast<uint4*>(&Bs[ldr][ldc + i*4]) = rb[i];
        }
        __syncthreads();
        if (k0 + 32 < DIM) {
            const int kq = (k0 + 32) >> 2;   // in uint4 units
            #pragma unroll
            for (int i = 0; i < 4; i++) { ra[i] = Ap[kq + i]; rb[i] = Bp[kq + i]; }
        }
        #pragma unroll
        for (int ks = 0; ks < 4; ks++) {
            uint32_t af[4][4], bf[4][2];
            #pragma unroll
            for (int mt = 0; mt < 4; mt++)
                ldsm_x4(af[mt][0], af[mt][1], af[mt][2], af[mt][3],
                        a_base + ((mt*16*36 + ks*8) << 2));
            #pragma unroll
            for (int nt2 = 0; nt2 < 2; nt2++) {
                uint32_t r0, r1, r2, r3;
                ldsm_x4(r0, r1, r2, r3, b_base + ((nt2*16*36 + ks*8) << 2));
                bf[2*nt2  ][0] = r0; bf[2*nt2+1][0] = r1;
                bf[2*nt2  ][1] = r2; bf[2*nt2+1][1] = r3;
            }
            #pragma unroll
            for (int mt = 0; mt < 4; mt++)
                #pragma unroll
                for (int nt = 0; nt < 4; nt++)
                    mma_tf32(acc[mt][nt], af[mt], bf[nt]);
        }
        __syncthreads();
    }

    #pragma unroll
    for (int nt = 0; nt < 4; nt++) {
        const int c = col0 + warpN*32 + nt*8 + 2*(lane & 3);
        const float b0v = bias[c];
        const float b1v = bias[c + 1];
        #pragma unroll
        for (int mt = 0; mt < 4; mt++) {
            const int r = row0 + warpM*64 + mt*16 + (lane >> 2);
            float2 o0 = make_float2(tf32r(acc[mt][nt][0] + b0v), tf32r(acc[mt][nt][1] + b1v));
            float2 o1 = make_float2(tf32r(acc[mt][nt][2] + b0v), tf32r(acc[mt][nt][3] + b1v));
            *reinterpret_cast<float2*>(Y + (size_t)r * DIM + c)       = o0;
            *reinterpret_cast<float2*>(Y + (size_t)(r + 8) * DIM + c) = o1;
        }
    }
}

// ============================================================
// TF32 V projection on the 64 reachable tokens per batch.
// ============================================================
__global__ __launch_bounds__(256) void k_gemm_v_t(const float* __restrict__ bv)
{
    __shared__ __align__(16) uint32_t As[128][36];
    __shared__ __align__(16) uint32_t Bs[128][36];

    const int bx = blockIdx.x;
    const int rt = bx / 6;
    const int ct = bx - rt * 6;

    const int tid  = threadIdx.x;
    const int lane = tid & 31;
    const int wid  = tid >> 5;
    const int warpM = wid & 1;
    const int warpN = wid >> 1;

    const int row0 = rt * 128;
    const int col0 = ct * 128;

    const int ldr = tid >> 1;
    const int ldc = (tid & 1) * 16;

    const int r_g = row0 + ldr;
    const int bb  = r_g >> 6;
    const int jj  = r_g & 63;
    const int token = 1 + (6 + (jj >> 3)) * GRID + (6 + (jj & 7));
    const uint4* Ap = reinterpret_cast<const uint4*>(g_x32 + (size_t)(bb * SEQ + token) * DIM + ldc);
    const uint4* Bp = reinterpret_cast<const uint4*>(g_wv32 + (size_t)(col0 + ldr) * DIM + ldc);

    const uint32_t As_addr = (uint32_t)__cvta_generic_to_shared(&As[0][0]);
    const uint32_t Bs_addr = (uint32_t)__cvta_generic_to_shared(&Bs[0][0]);
    const uint32_t a_base = As_addr + (((warpM*64 + (lane & 15)) * 36 + ((lane >> 4) << 2)) << 2);
    const uint32_t b_base = Bs_addr + (((warpN*32 + (lane & 15)) * 36 + ((lane >> 4) << 2)) << 2);

    float acc[4][4][4];
    #pragma unroll
    for (int mt = 0; mt < 4; mt++)
        #pragma unroll
        for (int nt = 0; nt < 4; nt++)
            #pragma unroll
            for (int i = 0; i < 4; i++) acc[mt][nt][i] = 0.f;

    uint4 ra[4], rb[4];
    #pragma unroll
    for (int i = 0; i < 4; i++) { ra[i] = Ap[i]; rb[i] = Bp[i]; }

    for (int k0 = 0; k0 < DIM; k0 += 32) {
        #pragma unroll
        for (int i = 0; i < 4; i++) {
            *reinterpret_cast<uint4*>(&As[ldr][ldc + i*4]) = ra[i];
            *reinterpret_cast<uint4*>(&Bs[ldr][ldc + i*4]) = rb[i];
        }
        __syncthreads();
        if (k0 + 32 < DIM) {
            const int kq = (k0 + 32) >> 2;
            #pragma unroll
            for (int i = 0; i < 4; i++) { ra[i] = Ap[kq + i]; rb[i] = Bp[kq + i]; }
        }
        #pragma unroll
        for (int ks = 0; ks < 4; ks++) {
            uint32_t af[4][4], bf[4][2];
            #pragma unroll
            for (int mt = 0; mt < 4; mt++)
                ldsm_x4(af[mt][0], af[mt][1], af[mt][2], af[mt][3],
                        a_base + ((mt*16*36 + ks*8) << 2));
            #pragma unroll
            for (int nt2 = 0; nt2 < 2; nt2++) {
                uint32_t r0, r1, r2, r3;
                ldsm_x4(r0, r1, r2, r3, b_base + ((nt2*16*36 + ks*8) << 2));
                bf[2*nt2  ][0] = r0; bf[2*nt2+1][0] = r1;
                bf[2*nt2  ][1] = r2; bf[2*nt2+1][1] = r3;
            }
            #pragma unroll
            for (int mt = 0; mt < 4; mt++)
                #pragma unroll
                for (int nt = 0; nt < 4; nt++)
                    mma_tf32(acc[mt][nt], af[mt], bf[nt]);
        }
        __syncthreads();
    }

    #pragma unroll
    for (int nt = 0; nt < 4; nt++) {
        const int c = col0 + warpN*32 + nt*8 + 2*(lane & 3);
        const float b0v = bv[c];
        const float b1v = bv[c + 1];
        #pragma unroll
        for (int mt = 0; mt < 4; mt++) {
            const int r = row0 + warpM*64 + mt*16 + (lane >> 2);
            float2 o0 = make_float2(acc[mt][nt][0] + b0v, acc[mt][nt][1] + b1v);
            float2 o1 = make_float2(acc[mt][nt][2] + b0v, acc[mt][nt][3] + b1v);
            *reinterpret_cast<float2*>(g_vs + (size_t)r * DIM + c)       = o0;
            *reinterpret_cast<float2*>(g_vs + (size_t)(r + 8) * DIM + c) = o1;
        }
    }
}

// ============================================================
// TF32 MLP layer 1: h1 = relu(concat(q_nc,k_nc) @ W1^T + b1)
// q/k already tf32-rounded; W1 pre-rounded. No in-loop cvt.
// Block 128x64; 8 warps = 4(M) x 2(N).
// ============================================================
__global__ __launch_bounds__(256) void k_gemm_h1_t(const float* __restrict__ b1)
{
    __shared__ __align__(16) uint32_t As[128][36];
    __shared__ __align__(16) uint32_t Bs[64][36];

    const int tid  = threadIdx.x;
    const int lane = tid & 31;
    const int wid  = tid >> 5;
    const int warpM = wid & 3;
    const int warpN = wid >> 2;

    const int row0 = blockIdx.x * 128;

    const int ldr = tid >> 1;
    const int ldc = (tid & 1) * 16;

    const int r_g = row0 + ldr;
    const int bb  = r_g / SN;
    const int tt  = r_g - bb * SN;
    const size_t aoff = (size_t)(bb * SEQ + tt + 1) * DIM + ldc;

    const int ldr2 = tid >> 2;            // 0..63
    const int ldc2 = (tid & 3) * 8;       // 0,8,16,24
    const bool bvalid = (ldr2 < H60);
    const float* Bp = g_w132 + (size_t)ldr2 * K2 + ldc2;

    const uint32_t As_addr = (uint32_t)__cvta_generic_to_shared(&As[0][0]);
    const uint32_t Bs_addr = (uint32_t)__cvta_generic_to_shared(&Bs[0][0]);
    const uint32_t a_base = As_addr + (((warpM*32 + (lane & 15)) * 36 + ((lane >> 4) << 2)) << 2);
    const uint32_t b_base = Bs_addr + (((warpN*32 + (lane & 15)) * 36 + ((lane >> 4) << 2)) << 2);

    float acc[2][4][4];
    #pragma unroll
    for (int mt = 0; mt < 2; mt++)
        #pragma unroll
        for (int nt = 0; nt < 4; nt++)
            #pragma unroll
            for (int i = 0; i < 4; i++) acc[mt][nt][i] = 0.f;

    const uint4 zero4 = make_uint4(0u, 0u, 0u, 0u);
    uint4 ra[4], rb[2];
    {
        const uint4* base = reinterpret_cast<const uint4*>(g_q + aoff);
        #pragma unroll
        for (int i = 0; i < 4; i++) ra[i] = base[i];
        #pragma unroll
        for (int i = 0; i < 2; i++)
            rb[i] = bvalid ? reinterpret_cast<const uint4*>(Bp)[i] : zero4;
    }

    for (int k0 = 0; k0 < K2; k0 += 32) {
        #pragma unroll
        for (int i = 0; i < 4; i++)
            *reinterpret_cast<uint4*>(&As[ldr][ldc + i*4]) = ra[i];
        #pragma unroll
        for (int i = 0; i < 2; i++)
            *reinterpret_cast<uint4*>(&Bs[ldr2][ldc2 + i*4]) = rb[i];
        __syncthreads();
        if (k0 + 32 < K2) {
            const int kn = k0 + 32;
            const uint4* base = reinterpret_cast<const uint4*>(
                (kn < DIM) ? (g_q + aoff + kn) : (g_k + aoff + kn - DIM));
            #pragma unroll
            for (int i = 0; i < 4; i++) ra[i] = base[i];
            #pragma unroll
            for (int i = 0; i < 2; i++)
                rb[i] = bvalid ? reinterpret_cast<const uint4*>(Bp + kn)[i] : zero4;
        }
        #pragma unroll
        for (int ks = 0; ks < 4; ks++) {
            uint32_t af[2][4], bf[4][2];
            #pragma unroll
            for (int mt = 0; mt < 2; mt++)
                ldsm_x4(af[mt][0], af[mt][1], af[mt][2], af[mt][3],
                        a_base + ((mt*16*36 + ks*8) << 2));
            #pragma unroll
            for (int nt2 = 0; nt2 < 2; nt2++) {
                uint32_t r0, r1, r2, r3;
                ldsm_x4(r0, r1, r2, r3, b_base + ((nt2*16*36 + ks*8) << 2));
                bf[2*nt2  ][0] = r0; bf[2*nt2+1][0] = r1;
                bf[2*nt2  ][1] = r2; bf[2*nt2+1][1] = r3;
            }
            #pragma unroll
            for (int mt = 0; mt < 2; mt++)
                #pragma unroll
                for (int nt = 0; nt < 4; nt++)
                    mma_tf32(acc[mt][nt], af[mt], bf[nt]);
        }
        __syncthreads();
    }

    #pragma unroll
    for (int nt = 0; nt < 4; nt++) {
        const int c = warpN*32 + nt*8 + 2*(lane & 3);
        const float b0v = (c     < H60) ? b1[c]     : 0.f;
        const float b1v = (c + 1 < H60) ? b1[c + 1] : 0.f;
        #pragma unroll
        for (int mt = 0; mt < 2; mt++) {
            const int r = row0 + warpM*32 + mt*16 + (lane >> 2);
            if (c < H60) {
                g_h1[(size_t)r * H60 + c]       = fmaxf(acc[mt][nt][0] + b0v, 0.f);
                g_h1[(size_t)(r + 8) * H60 + c] = fmaxf(acc[mt][nt][2] + b0v, 0.f);
            }
            if (c + 1 < H60) {
                g_h1[(size_t)r * H60 + c + 1]       = fmaxf(acc[mt][nt][1] + b1v, 0.f);
                g_h1[(size_t)(r + 8) * H60 + c + 1] = fmaxf(acc[mt][nt][3] + b1v, 0.f);
            }
        }
    }
}

// ============================================================
// MLP layers 2+3 (unchanged)
// ============================================================
__global__ __launch_bounds__(256) void k_mlp23(
    const float* __restrict__ W2, const float* __restrict__ b2,
    const float* __restrict__ W3, const float* __restrict__ b3)
{
    __shared__ float W2s[60*61], W3s[120], b2s[60], b3s[2], h1s[16][60], h2s[16][60];
    const int tid = threadIdx.x;
    for (int i = tid; i < 3600; i += 256) { int rr = i / 60, cc = i - rr * 60; W2s[rr*61+cc] = W2[i]; }
    if (tid < 120) W3s[tid] = W3[tid];
    if (tid < 60)  b2s[tid] = b2[tid];
    if (tid < 2)   b3s[tid] = b3[tid];
    const int r0 = blockIdx.x * 16;
    for (int i = tid; i < 960; i += 256) { int t = i / 60, c = i - t * 60; h1s[t][c] = g_h1[(size_t)(r0+t)*H60 + c]; }
    __syncthreads();
    const int tg = tid >> 6, f = tid & 63;
    if (f < H60) {
        float a0 = b2s[f], a1 = a0, a2 = a0, a3 = a0;
        #pragma unroll 4
        for (int g = 0; g < H60; g++) {
            const float w = W2s[f*61 + g];
            a0 = fmaf(w, h1s[tg*4+0][g], a0); a1 = fmaf(w, h1s[tg*4+1][g], a1);
            a2 = fmaf(w, h1s[tg*4+2][g], a2); a3 = fmaf(w, h1s[tg*4+3][g], a3);
        }
        h2s[tg*4+0][f] = fmaxf(a0, 0.f); h2s[tg*4+1][f] = fmaxf(a1, 0.f);
        h2s[tg*4+2][f] = fmaxf(a2, 0.f); h2s[tg*4+3][f] = fmaxf(a3, 0.f);
    }
    __syncthreads();
    if (tid < 32) {
        int t2 = tid >> 1, c = tid & 1;
        float s = b3s[c];
        #pragma unroll 4
        for (int g = 0; g < H60; g++) s = fmaf(W3s[c*60+g], h2s[t2][g], s);
        g_sample[(size_t)(r0+t2)*2 + c] = 1.f / (1.f + expf(-s));
    }
}

__global__ void k_coords()
{
    const int id = blockIdx.x * 256 + threadIdx.x;
    const int b = id / SN, p = id - b * SN;
    const int q1 = 2 * p, q2 = 2 * p + 1;
    float gx = (q1 < SN) ? g_sample[(size_t)(b*SN+q1)*2+0] : g_sample[(size_t)(b*SN+q1-SN)*2+1];
    float gy = (q2 < SN) ? g_sample[(size_t)(b*SN+q2)*2+0] : g_sample[(size_t)(b*SN+q2-SN)*2+1];
    g_coords[(size_t)id*2+0] = ((gx + 1.f) * (float)GRID - 1.f) * 0.5f;
    g_coords[(size_t)id*2+1] = ((gy + 1.f) * (float)GRID - 1.f) * 0.5f;
}

__global__ __launch_bounds__(256) void k_epilogue(float* __restrict__ out)
{
    const int bs = blockIdx.x, b = bs / SEQ, s = bs - b * SEQ;
    const int tid = threadIdx.x, lane = tid & 31, wid = tid >> 5;
    __shared__ float red[8];
    __shared__ float sigsh;
    const size_t qbase = (size_t)bs * DIM;
    float w[4]; size_t rowk[4], rowv[4]; bool vk[4], vv[4];

    if (s > 0) {
        const int p = s - 1;
        const float ix = g_coords[(size_t)(b*SN+p)*2+0];
        const float iy = g_coords[(size_t)(b*SN+p)*2+1];
        const float ix0f = floorf(ix), iy0f = floorf(iy);
        const float wx1 = ix - ix0f, wx0 = 1.f - wx1;
        const float wy1 = iy - iy0f, wy0 = 1.f - wy1;
        const int x0 = (int)ix0f, y0 = (int)iy0f;
        const int xs[4] = {x0, x0+1, x0, x0+1};
        const int ys[4] = {y0, y0, y0+1, y0+1};
        const float ws[4] = {wy0*wx0, wy0*wx1, wy1*wx0, wy1*wx1};
        #pragma unroll
        for (int c = 0; c < 4; c++) {
            const int x = xs[c], y = ys[c];
            const bool v = (x >= 0) && (x <= GRID-1) && (y >= 0) && (y <= GRID-1);
            vk[c] = v; w[c] = ws[c];
            rowk[c] = v ? (size_t)(b * SEQ + 1 + y * GRID + x) * DIM : 0;
            const bool v2 = v && (x >= 6) && (y >= 6);
            vv[c] = v2;
            rowv[c] = v2 ? (size_t)(b * 64 + (y-6)*8 + (x-6)) * DIM : 0;
        }
    }

    float part = 0.f, svreg[3];
    #pragma unroll
    for (int it = 0; it < 3; it++) {
        const int d = tid + it * 256;
        float skd, svd;
        if (s == 0) { skd = 1.f; svd = 1.f; }
        else {
            skd = 0.f; svd = 0.f;
            #pragma unroll
            for (int c = 0; c < 4; c++) {
                if (vk[c]) skd = fmaf(w[c], g_k[rowk[c] + d], skd);
                if (vv[c]) svd = fmaf(w[c], g_vs[rowv[c] + d], svd);
            }
        }
        svreg[it] = svd;
        part = fmaf(skd, g_q[qbase + d], part);
    }
    #pragma unroll
    for (int off = 16; off > 0; off >>= 1) part += __shfl_xor_sync(0xffffffffu, part, off);
    if (lane == 0) red[wid] = part;
    __syncthreads();
    if (tid == 0) {
        float sum = 0.f;
        #pragma unroll
        for (int i = 0; i < 8; i++) sum += red[i];
        sigsh = 1.f / (1.f + expf(-0.01f * sum));
    }
    __syncthreads();
    const float sg = sigsh;
    #pragma unroll
    for (int it = 0; it < 3; it++) out[qbase + tid + it*256] = sg * svreg[it];
}

extern "C" void kernel_launch(void* const* d_in, const int* in_sizes, int n_in,
                              void* d_out, int out_size)
{
    const float* x  = (const float*)d_in[0];
    const float* Wq = (const float*)d_in[2];  const float* bq = (const float*)d_in[3];
    const float* Wk = (const float*)d_in[4];  const float* bk = (const float*)d_in[5];
    const float* Wv = (const float*)d_in[6];  const float* bv = (const float*)d_in[7];
    const float* W1 = (const float*)d_in[8];  const float* b1 = (const float*)d_in[9];
    const float* W2 = (const float*)d_in[10]; const float* b2 = (const float*)d_in[11];
    const float* W3 = (const float*)d_in[12]; const float* b3 = (const float*)d_in[13];
    float* out = (float*)d_out;

    k_cvt<<<39642, 256>>>((const float4*)x, (const float4*)Wq, (const float4*)Wk,
                          (const float4*)Wv, (const float4*)W1);
    k_gemm_qk_t<<<394 * 12, 256>>>(bq, bk);
    k_gemm_v_t<<<128 * 6, 256>>>(bv);
    k_gemm_h1_t<<<392, 256>>>(b1);
    k_mlp23<<<3136, 256>>>(W2, b2, W3, b3);
    k_coords<<<196, 256>>>();
    k_epilogue<<<MQK, 256>>>(out);
}